// round 10
// baseline (speedup 1.0000x reference)
#include <cuda_runtime.h>
#include <cuda_bf16.h>
#include <math_constants.h>
#include <cstdint>

// ----------------------------------------------------------------------------
// Window VQ via mma.sync bf16 tensor cores (base ISA, works on sm_100 target).
//   argmin_k ||z - c_k||^2 == argmax_k ( z.c_k - 0.5*||c_k||^2 )
// fp32 emulated as 3-way bf16 split (x = x1+x2+x3); 6 cross-products
// {11,12,21,22,13,31} accumulated in fp32 -> error ~2e-7, exact argmin.
//
// R10 = R9 + latency engineering:
//  - accumulators split by k-phase -> 4 independent HMMA chains per warp
//  - two disjoint B register sets, software-pipelined across the 3 B-splits
//    (no WAR serialization between LDSM batches and MMA passes)
// ----------------------------------------------------------------------------

#define D       128
#define BMW     128     // windows per CTA
#define NTE     64      // codebook entries per staged tile
#define NTHR    256

// smem byte offsets: A 96KB | B0 48KB | B1 48KB | cnorm 8KB = 200KB
#define OFF_A    0
#define OFF_B0   98304
#define OFF_B1   147456
#define OFF_CN   196608
#define SMEM_TOTAL 204800

__device__ float g_cnorm[4096];
// packed B splits: [nt][s 0..2][j 0..7][kt 0..15][r 0..7][c 0..7] bf16, 1.5MB
__device__ __align__(16) __nv_bfloat16 g_Bpk[32 * 3 * 8 * 16 * 64];

// ---------------------------------------------------------------------------
__global__ void cnorm_kernel(const float* __restrict__ cb, int K) {
    int row  = blockIdx.x * 8 + (threadIdx.x >> 5);
    int lane = threadIdx.x & 31;
    if (row < K) {
        const float4 v = reinterpret_cast<const float4*>(cb + (size_t)row * D)[lane];
        float s = v.x * v.x + v.y * v.y + v.z * v.z + v.w * v.w;
        #pragma unroll
        for (int o = 16; o; o >>= 1) s += __shfl_xor_sync(0xffffffffu, s, o);
        if (lane == 0) g_cnorm[row] = 0.5f * s;
    }
}

__device__ __forceinline__ void split3(float x, __nv_bfloat16& h1,
                                       __nv_bfloat16& h2, __nv_bfloat16& h3) {
    h1 = __float2bfloat16(x);
    const float r1 = x - __bfloat162float(h1);
    h2 = __float2bfloat16(r1);
    h3 = __float2bfloat16(r1 - __bfloat162float(h2));
}

// Pack codebook: entry n, dim k -> tile layout per (nt, split, j=n8, kt=k/8):
// 8x8 bf16 tile (row r = n%8, col c = k%8) stored as 128B contiguous.
__global__ void pack_cb_kernel(const float* __restrict__ cb, int K) {
    const int idx = blockIdx.x * NTHR + threadIdx.x;
    if (idx >= K * D) return;
    const int n = idx >> 7, k = idx & 127;
    __nv_bfloat16 h1, h2, h3;
    split3(cb[idx], h1, h2, h3);
    const int nt = n >> 6, j = (n >> 3) & 7, r = n & 7;
    const int kt = k >> 3, c = k & 7;
    const size_t off = (size_t)nt * 24576 + j * 1024 + kt * 64 + r * 8 + c;
    g_Bpk[off]         = h1;
    g_Bpk[off + 8192]  = h2;
    g_Bpk[off + 16384] = h3;
}

// ---------------------------------------------------------------------------
#define LDSM4(r0, r1, r2, r3, a) \
    asm volatile("ldmatrix.sync.aligned.m8n8.x4.shared.b16 {%0,%1,%2,%3}, [%4];" \
                 : "=r"(r0), "=r"(r1), "=r"(r2), "=r"(r3) : "r"(a))

#define MMA(ac, A0, A1, A2, A3, B0, B1) \
    asm volatile("mma.sync.aligned.m16n8k16.row.col.f32.bf16.bf16.f32 " \
                 "{%0,%1,%2,%3},{%4,%5,%6,%7},{%8,%9},{%0,%1,%2,%3};" \
                 : "+f"(ac[0]), "+f"(ac[1]), "+f"(ac[2]), "+f"(ac[3]) \
                 : "r"(A0), "r"(A1), "r"(A2), "r"(A3), "r"(B0), "r"(B1))

__device__ __forceinline__ uint32_t smem_u32(const void* p) {
    uint32_t a;
    asm("{ .reg .u64 t; cvta.to.shared.u64 t, %1; cvt.u32.u64 %0, t; }" : "=r"(a) : "l"(p));
    return a;
}
__device__ __forceinline__ void cp_async16(uint32_t saddr, const void* g) {
    asm volatile("cp.async.cg.shared.global [%0], [%1], 16;" :: "r"(saddr), "l"(g));
}

// load 8 k-step B fragments (16 regs) for one n8 region (2KB of tiles).
// addr MUST already include lane*16 (per-lane row address for ldmatrix).
__device__ __forceinline__ void load_bfrags(uint32_t* b, uint32_t addr) {
    #pragma unroll
    for (int q = 0; q < 4; ++q)
        LDSM4(b[q * 4 + 0], b[q * 4 + 1], b[q * 4 + 2], b[q * 4 + 3], addr + q * 512);
}

// one split pass with k-phase-split accumulators:
// kk 0..3 -> accA, kk 4..7 -> accB (4 independent HMMA chains per warp).
__device__ __forceinline__ void mma_pass2(float (*accA)[4], float (*accB)[4],
                                          const uint32_t (*af)[4],
                                          const uint32_t* b0, const uint32_t* b1) {
    #pragma unroll
    for (int kk = 0; kk < 4; ++kk) {
        MMA(accA[0], af[kk][0], af[kk][1], af[kk][2], af[kk][3], b0[2 * kk], b0[2 * kk + 1]);
        MMA(accA[1], af[kk][0], af[kk][1], af[kk][2], af[kk][3], b1[2 * kk], b1[2 * kk + 1]);
    }
    #pragma unroll
    for (int kk = 4; kk < 8; ++kk) {
        MMA(accB[0], af[kk][0], af[kk][1], af[kk][2], af[kk][3], b0[2 * kk], b0[2 * kk + 1]);
        MMA(accB[1], af[kk][0], af[kk][1], af[kk][2], af[kk][3], b1[2 * kk], b1[2 * kk + 1]);
    }
}

// ---------------------------------------------------------------------------
__global__ __launch_bounds__(NTHR, 1)
void vq_mma_kernel(const float* __restrict__ ze,
                   const float* __restrict__ cb,
                   float* __restrict__ out,
                   int ntiles) {
    extern __shared__ __align__(16) char smem[];
    float* Cn = reinterpret_cast<float*>(smem + OFF_CN);

    const uint32_t sbase = smem_u32(smem);
    const int tid  = threadIdx.x;
    const int w    = tid >> 5;
    const int lane = tid & 31;

    // ---- 1. build A split tiles in smem (ldmatrix-packed, mma subtile order) ----
    {
        const float* zsrc = ze + (size_t)blockIdx.x * (BMW * D);
        for (int i = tid; i < BMW * D; i += NTHR) {
            const int m = i >> 7, k = i & 127;
            __nv_bfloat16 h1, h2, h3;
            split3(zsrc[i], h1, h2, h3);
            const int t = ((m >> 3) & 1) | (((k >> 3) & 1) << 1);
            const int base = (m >> 4) * 12288 + (k >> 4) * 512 + t * 128
                           + (m & 7) * 16 + (k & 7) * 2;
            *reinterpret_cast<__nv_bfloat16*>(smem + base)        = h1;
            *reinterpret_cast<__nv_bfloat16*>(smem + base + 4096) = h2;
            *reinterpret_cast<__nv_bfloat16*>(smem + base + 8192) = h3;
        }
        for (int i = tid; i < ntiles * NTE; i += NTHR) Cn[i] = g_cnorm[i];
    }
    __syncthreads();

    // ---- 2. A1/A2 fragments resident in registers ----
    uint32_t a1f[8][4], a2f[8][4];
    const uint32_t abase = sbase + w * 12288 + lane * 16;
    #pragma unroll
    for (int kk = 0; kk < 8; ++kk)
        LDSM4(a1f[kk][0], a1f[kk][1], a1f[kk][2], a1f[kk][3], abase + kk * 512);
    #pragma unroll
    for (int kk = 0; kk < 8; ++kk)
        LDSM4(a2f[kk][0], a2f[kk][1], a2f[kk][2], a2f[kk][3], abase + 4096 + kk * 512);

    // ---- 3. prologue: stage B tile 0 ----
    {
        const char* src = reinterpret_cast<const char*>(g_Bpk);
        #pragma unroll
        for (int u = 0; u < 12; ++u)
            cp_async16(sbase + OFF_B0 + u * 4096 + tid * 16, src + u * 4096 + tid * 16);
        asm volatile("cp.async.commit_group;");
    }

    float best[2] = {-CUDART_INF_F, -CUDART_INF_F};
    int   bidx[2] = {0, 0};

    for (int nt = 0; nt < ntiles; ++nt) {
        asm volatile("cp.async.wait_group 0;");
        __syncthreads();

        if (nt + 1 < ntiles) {
            const char* src = reinterpret_cast<const char*>(g_Bpk) + (size_t)(nt + 1) * 49152;
            const uint32_t dst = sbase + (((nt + 1) & 1) ? OFF_B1 : OFF_B0);
            #pragma unroll
            for (int u = 0; u < 12; ++u)
                cp_async16(dst + u * 4096 + tid * 16, src + u * 4096 + tid * 16);
            asm volatile("cp.async.commit_group;");
        }

        // per-lane base inside the current B buffer
        const uint32_t bb = sbase + ((nt & 1) ? OFF_B1 : OFF_B0) + lane * 16;
        const int ntbase = nt * NTE;

        #pragma unroll
        for (int jj = 0; jj < 4; ++jj) {
            float accA[2][4] = {{0.f, 0.f, 0.f, 0.f}, {0.f, 0.f, 0.f, 0.f}};
            float accB[2][4] = {{0.f, 0.f, 0.f, 0.f}, {0.f, 0.f, 0.f, 0.f}};
            uint32_t bA0[16], bA1[16], bB0[16], bB1[16];

            // issue LDSMs for split s0 (set A) AND split s1 (set B) up front
            load_bfrags(bA0, bb + (2 * jj) * 2048);
            load_bfrags(bA1, bb + (2 * jj + 1) * 2048);
            load_bfrags(bB0, bb + 16384 + (2 * jj) * 2048);
            load_bfrags(bB1, bb + 16384 + (2 * jj + 1) * 2048);

            // passes on split s0: (A1,B1), (A2,B1), (A3,B1)
            mma_pass2(accA, accB, a1f, bA0, bA1);
            mma_pass2(accA, accB, a2f, bA0, bA1);
            #pragma unroll
            for (int kk = 0; kk < 8; ++kk) {     // A3 from smem
                uint32_t t0, t1, t2, t3;
                LDSM4(t0, t1, t2, t3, abase + 8192 + kk * 512);
                if (kk < 4) {
                    MMA(accA[0], t0, t1, t2, t3, bA0[2 * kk], bA0[2 * kk + 1]);
                    MMA(accA[1], t0, t1, t2, t3, bA1[2 * kk], bA1[2 * kk + 1]);
                } else {
                    MMA(accB[0], t0, t1, t2, t3, bA0[2 * kk], bA0[2 * kk + 1]);
                    MMA(accB[1], t0, t1, t2, t3, bA1[2 * kk], bA1[2 * kk + 1]);
                }
            }

            // split s2 into set A (WAR on bA resolved: s0 passes already done)
            load_bfrags(bA0, bb + 32768 + (2 * jj) * 2048);
            load_bfrags(bA1, bb + 32768 + (2 * jj + 1) * 2048);

            // passes on split s1: (A1,B2), (A2,B2)
            mma_pass2(accA, accB, a1f, bB0, bB1);
            mma_pass2(accA, accB, a2f, bB0, bB1);

            // pass on split s2: (A1,B3)
            mma_pass2(accA, accB, a1f, bA0, bA1);

            // ---- epilogue: phase-sum, scores + running argmax (ascending n) ----
            #pragma unroll
            for (int js = 0; js < 2; ++js) {
                const int n0 = ntbase + (2 * jj + js) * 8 + 2 * (lane & 3);
                const float2 cn2 = *reinterpret_cast<const float2*>(&Cn[n0]);
                const float s00 = (accA[js][0] + accB[js][0]) - cn2.x;   // row g,   n0
                const float s01 = (accA[js][1] + accB[js][1]) - cn2.y;   // row g,   n0+1
                const float s10 = (accA[js][2] + accB[js][2]) - cn2.x;   // row g+8, n0
                const float s11 = (accA[js][3] + accB[js][3]) - cn2.y;
                if (s00 > best[0]) { best[0] = s00; bidx[0] = n0; }
                if (s01 > best[0]) { best[0] = s01; bidx[0] = n0 + 1; }
                if (s10 > best[1]) { best[1] = s10; bidx[1] = n0; }
                if (s11 > best[1]) { best[1] = s11; bidx[1] = n0 + 1; }
            }
        }
    }

    // ---- reduce 4 candidates per window (lanes l%4), reuse B0 region ----
    float* sF   = reinterpret_cast<float*>(smem + OFF_B0);         // [128][4]
    int*   sI   = reinterpret_cast<int*>(smem + OFF_B0 + 2048);
    int*   widx = reinterpret_cast<int*>(smem + OFF_B0 + 4096);
    __syncthreads();      // all warps done reading B buffers
    {
        const int m0 = 16 * w + (lane >> 2);
        const int q  = lane & 3;
        sF[m0 * 4 + q] = best[0];  sI[m0 * 4 + q] = bidx[0];
        sF[(m0 + 8) * 4 + q] = best[1];  sI[(m0 + 8) * 4 + q] = bidx[1];
    }
    __syncthreads();
    if (tid < BMW) {
        float bs = sF[tid * 4];
        int   bi = sI[tid * 4];
        #pragma unroll
        for (int q = 1; q < 4; ++q) {
            const float s  = sF[tid * 4 + q];
            const int   ix = sI[tid * 4 + q];
            if (s > bs || (s == bs && ix < bi)) { bs = s; bi = ix; }
        }
        widx[tid] = bi;
    }
    __syncthreads();

    // ---- gather winning codebook rows (L2-hot) ----
    const float4* cb4  = reinterpret_cast<const float4*>(cb);
    float4*       out4 = reinterpret_cast<float4*>(out) + (size_t)blockIdx.x * (BMW * 32);
    #pragma unroll
    for (int i = 0; i < 16; ++i) {
        const int f = i * 256 + tid;          // 0..4095
        const int wv = f >> 5, c = f & 31;
        out4[f] = __ldg(&cb4[(size_t)widx[wv] * 32 + c]);
    }
}

// ---------------------------------------------------------------------------
extern "C" void kernel_launch(void* const* d_in, const int* in_sizes, int n_in,
                              void* d_out, int out_size) {
    const float* ze = (const float*)d_in[0];
    const float* cb = (const float*)d_in[1];
    float* out = (float*)d_out;

    const int M = in_sizes[0] / D;   // 65536
    const int K = in_sizes[1] / D;   // 2048

    cudaFuncSetAttribute(vq_mma_kernel, cudaFuncAttributeMaxDynamicSharedMemorySize,
                         SMEM_TOTAL);

    cnorm_kernel<<<(K + 7) / 8, NTHR>>>(cb, K);
    pack_cb_kernel<<<(K * D + NTHR - 1) / NTHR, NTHR>>>(cb, K);
    vq_mma_kernel<<<M / BMW, NTHR, SMEM_TOTAL>>>(ze, cb, out, K / NTE);
}

// round 11
// speedup vs baseline: 1.1056x; 1.1056x over previous
#include <cuda_runtime.h>
#include <cuda_bf16.h>
#include <math_constants.h>
#include <cstdint>

// ----------------------------------------------------------------------------
// Window VQ via mma.sync bf16 tensor cores (base ISA, works on sm_100 target).
//   argmin_k ||z - c_k||^2 == argmax_k ( z.c_k - 0.5*||c_k||^2 )
// fp32 emulated as 3-way bf16 split (x = x1+x2+x3); 6 cross-products
// {11,12,21,22,13,31} accumulated in fp32 -> error ~2e-7, exact argmin.
//
// R11 = R9 scheduling (lean registers) + BMW=64: grid 1024 -> 6.92 waves
// (98.8% wave utilization vs 86.5% at grid 512). Warp = (m-tile, n-half).
// ----------------------------------------------------------------------------

#define D       128
#define BMW     64      // windows per CTA
#define NTE     64      // codebook entries per staged tile
#define NTHR    256

// smem byte offsets: A 48KB | B0 48KB | B1 48KB | cnorm 8KB = 152KB
#define OFF_A    0
#define OFF_B0   49152
#define OFF_B1   98304
#define OFF_CN   147456
#define SMEM_TOTAL 155648

__device__ float g_cnorm[4096];
// packed B splits: [nt][s 0..2][j 0..7][kt 0..15][r 0..7][c 0..7] bf16, 1.5MB
__device__ __align__(16) __nv_bfloat16 g_Bpk[32 * 3 * 8 * 16 * 64];

// ---------------------------------------------------------------------------
__global__ void cnorm_kernel(const float* __restrict__ cb, int K) {
    int row  = blockIdx.x * 8 + (threadIdx.x >> 5);
    int lane = threadIdx.x & 31;
    if (row < K) {
        const float4 v = reinterpret_cast<const float4*>(cb + (size_t)row * D)[lane];
        float s = v.x * v.x + v.y * v.y + v.z * v.z + v.w * v.w;
        #pragma unroll
        for (int o = 16; o; o >>= 1) s += __shfl_xor_sync(0xffffffffu, s, o);
        if (lane == 0) g_cnorm[row] = 0.5f * s;
    }
}

__device__ __forceinline__ void split3(float x, __nv_bfloat16& h1,
                                       __nv_bfloat16& h2, __nv_bfloat16& h3) {
    h1 = __float2bfloat16(x);
    const float r1 = x - __bfloat162float(h1);
    h2 = __float2bfloat16(r1);
    h3 = __float2bfloat16(r1 - __bfloat162float(h2));
}

// Pack codebook: entry n, dim k -> tile layout per (nt, split, j=n8, kt=k/8):
// 8x8 bf16 tile (row r = n%8, col c = k%8) stored as 128B contiguous.
__global__ void pack_cb_kernel(const float* __restrict__ cb, int K) {
    const int idx = blockIdx.x * NTHR + threadIdx.x;
    if (idx >= K * D) return;
    const int n = idx >> 7, k = idx & 127;
    __nv_bfloat16 h1, h2, h3;
    split3(cb[idx], h1, h2, h3);
    const int nt = n >> 6, j = (n >> 3) & 7, r = n & 7;
    const int kt = k >> 3, c = k & 7;
    const size_t off = (size_t)nt * 24576 + j * 1024 + kt * 64 + r * 8 + c;
    g_Bpk[off]         = h1;
    g_Bpk[off + 8192]  = h2;
    g_Bpk[off + 16384] = h3;
}

// ---------------------------------------------------------------------------
#define LDSM4(r0, r1, r2, r3, a) \
    asm volatile("ldmatrix.sync.aligned.m8n8.x4.shared.b16 {%0,%1,%2,%3}, [%4];" \
                 : "=r"(r0), "=r"(r1), "=r"(r2), "=r"(r3) : "r"(a))

#define MMA(ac, A0, A1, A2, A3, B0, B1) \
    asm volatile("mma.sync.aligned.m16n8k16.row.col.f32.bf16.bf16.f32 " \
                 "{%0,%1,%2,%3},{%4,%5,%6,%7},{%8,%9},{%0,%1,%2,%3};" \
                 : "+f"(ac[0]), "+f"(ac[1]), "+f"(ac[2]), "+f"(ac[3]) \
                 : "r"(A0), "r"(A1), "r"(A2), "r"(A3), "r"(B0), "r"(B1))

__device__ __forceinline__ uint32_t smem_u32(const void* p) {
    uint32_t a;
    asm("{ .reg .u64 t; cvta.to.shared.u64 t, %1; cvt.u32.u64 %0, t; }" : "=r"(a) : "l"(p));
    return a;
}
__device__ __forceinline__ void cp_async16(uint32_t saddr, const void* g) {
    asm volatile("cp.async.cg.shared.global [%0], [%1], 16;" :: "r"(saddr), "l"(g));
}

// load 8 k-step B fragments (16 regs) for one n8 region (2KB of tiles).
// addr MUST already include lane*16 (per-lane row address for ldmatrix).
__device__ __forceinline__ void load_bfrags(uint32_t* b, uint32_t addr) {
    #pragma unroll
    for (int q = 0; q < 4; ++q)
        LDSM4(b[q * 4 + 0], b[q * 4 + 1], b[q * 4 + 2], b[q * 4 + 3], addr + q * 512);
}

// one split-pair pass: 8 k-steps x 2 n8 accumulators
__device__ __forceinline__ void mma_pass(float (*acc)[4], const uint32_t (*af)[4],
                                         const uint32_t* b0, const uint32_t* b1) {
    #pragma unroll
    for (int kk = 0; kk < 8; ++kk) {
        MMA(acc[0], af[kk][0], af[kk][1], af[kk][2], af[kk][3], b0[2 * kk], b0[2 * kk + 1]);
        MMA(acc[1], af[kk][0], af[kk][1], af[kk][2], af[kk][3], b1[2 * kk], b1[2 * kk + 1]);
    }
}

// ---------------------------------------------------------------------------
// Warp w: m-tile = w&3 (rows 16*(w&3)..+15), n-half = w>>2 (n8 groups
// 4*(w>>2)..+3 of each staged tile).
// ---------------------------------------------------------------------------
__global__ __launch_bounds__(NTHR, 1)
void vq_mma_kernel(const float* __restrict__ ze,
                   const float* __restrict__ cb,
                   float* __restrict__ out,
                   int ntiles) {
    extern __shared__ __align__(16) char smem[];
    float* Cn = reinterpret_cast<float*>(smem + OFF_CN);

    const uint32_t sbase = smem_u32(smem);
    const int tid  = threadIdx.x;
    const int w    = tid >> 5;
    const int lane = tid & 31;
    const int nhalf = w >> 2;

    // ---- 1. build A split tiles in smem (ldmatrix-packed, mma subtile order) ----
    {
        const float* zsrc = ze + (size_t)blockIdx.x * (BMW * D);
        for (int i = tid; i < BMW * D; i += NTHR) {
            const int m = i >> 7, k = i & 127;
            __nv_bfloat16 h1, h2, h3;
            split3(zsrc[i], h1, h2, h3);
            const int t = ((m >> 3) & 1) | (((k >> 3) & 1) << 1);
            const int base = (m >> 4) * 4096 + (k >> 4) * 512 + t * 128
                           + (m & 7) * 16 + (k & 7) * 2;
            *reinterpret_cast<__nv_bfloat16*>(smem + base)         = h1;
            *reinterpret_cast<__nv_bfloat16*>(smem + base + 16384) = h2;
            *reinterpret_cast<__nv_bfloat16*>(smem + base + 32768) = h3;
        }
        for (int i = tid; i < ntiles * NTE; i += NTHR) Cn[i] = g_cnorm[i];
    }
    __syncthreads();

    // ---- 2. A1/A2 fragments resident in registers (m-tile = w&3) ----
    uint32_t a1f[8][4], a2f[8][4];
    const uint32_t abase = sbase + (w & 3) * 4096 + lane * 16;
    #pragma unroll
    for (int kk = 0; kk < 8; ++kk)
        LDSM4(a1f[kk][0], a1f[kk][1], a1f[kk][2], a1f[kk][3], abase + kk * 512);
    #pragma unroll
    for (int kk = 0; kk < 8; ++kk)
        LDSM4(a2f[kk][0], a2f[kk][1], a2f[kk][2], a2f[kk][3], abase + 16384 + kk * 512);

    // ---- 3. prologue: stage B tile 0 ----
    {
        const char* src = reinterpret_cast<const char*>(g_Bpk);
        #pragma unroll
        for (int u = 0; u < 12; ++u)
            cp_async16(sbase + OFF_B0 + u * 4096 + tid * 16, src + u * 4096 + tid * 16);
        asm volatile("cp.async.commit_group;");
    }

    float best[2] = {-CUDART_INF_F, -CUDART_INF_F};
    int   bidx[2] = {0, 0};

    for (int nt = 0; nt < ntiles; ++nt) {
        asm volatile("cp.async.wait_group 0;");
        __syncthreads();

        if (nt + 1 < ntiles) {
            const char* src = reinterpret_cast<const char*>(g_Bpk) + (size_t)(nt + 1) * 49152;
            const uint32_t dst = sbase + (((nt + 1) & 1) ? OFF_B1 : OFF_B0);
            #pragma unroll
            for (int u = 0; u < 12; ++u)
                cp_async16(dst + u * 4096 + tid * 16, src + u * 4096 + tid * 16);
            asm volatile("cp.async.commit_group;");
        }

        // per-lane base inside the current B buffer
        const uint32_t bb = sbase + ((nt & 1) ? OFF_B1 : OFF_B0) + lane * 16;
        const int ntbase = nt * NTE;

        #pragma unroll
        for (int jj = 0; jj < 2; ++jj) {
            const int g0 = nhalf * 4 + 2 * jj;            // first n8 group
            float acc[2][4] = {{0.f, 0.f, 0.f, 0.f}, {0.f, 0.f, 0.f, 0.f}};
            uint32_t b0r[16], b1r[16];

            // split s=0 of B: pairs (A1,B1), (A2,B1), (A3,B1)
            load_bfrags(b0r, bb + g0 * 2048);
            load_bfrags(b1r, bb + (g0 + 1) * 2048);
            mma_pass(acc, a1f, b0r, b1r);
            mma_pass(acc, a2f, b0r, b1r);
            #pragma unroll
            for (int kk = 0; kk < 8; ++kk) {     // A3 from smem
                uint32_t t0, t1, t2, t3;
                LDSM4(t0, t1, t2, t3, abase + 32768 + kk * 512);
                MMA(acc[0], t0, t1, t2, t3, b0r[2 * kk], b0r[2 * kk + 1]);
                MMA(acc[1], t0, t1, t2, t3, b1r[2 * kk], b1r[2 * kk + 1]);
            }

            // split s=1 of B: pairs (A1,B2), (A2,B2)
            load_bfrags(b0r, bb + 16384 + g0 * 2048);
            load_bfrags(b1r, bb + 16384 + (g0 + 1) * 2048);
            mma_pass(acc, a1f, b0r, b1r);
            mma_pass(acc, a2f, b0r, b1r);

            // split s=2 of B: pair (A1,B3)
            load_bfrags(b0r, bb + 32768 + g0 * 2048);
            load_bfrags(b1r, bb + 32768 + (g0 + 1) * 2048);
            mma_pass(acc, a1f, b0r, b1r);

            // ---- epilogue: scores + running argmax (ascending n) ----
            #pragma unroll
            for (int js = 0; js < 2; ++js) {
                const int n0 = ntbase + (g0 + js) * 8 + 2 * (lane & 3);
                const float2 cn2 = *reinterpret_cast<const float2*>(&Cn[n0]);
                const float s00 = acc[js][0] - cn2.x;   // row g,   n0
                const float s01 = acc[js][1] - cn2.y;   // row g,   n0+1
                const float s10 = acc[js][2] - cn2.x;   // row g+8, n0
                const float s11 = acc[js][3] - cn2.y;
                if (s00 > best[0]) { best[0] = s00; bidx[0] = n0; }
                if (s01 > best[0]) { best[0] = s01; bidx[0] = n0 + 1; }
                if (s10 > best[1]) { best[1] = s10; bidx[1] = n0; }
                if (s11 > best[1]) { best[1] = s11; bidx[1] = n0 + 1; }
            }
        }
    }

    // ---- reduce 8 candidates per window (4 lane-quads x 2 n-halves) ----
    float* sF   = reinterpret_cast<float*>(smem + OFF_B0);         // [64][8]
    int*   sI   = reinterpret_cast<int*>(smem + OFF_B0 + 2048);
    int*   widx = reinterpret_cast<int*>(smem + OFF_B0 + 4096);
    __syncthreads();      // all warps done reading B buffers
    {
        const int m0  = 16 * (w & 3) + (lane >> 2);
        const int col = nhalf * 4 + (lane & 3);
        sF[m0 * 8 + col] = best[0];        sI[m0 * 8 + col] = bidx[0];
        sF[(m0 + 8) * 8 + col] = best[1];  sI[(m0 + 8) * 8 + col] = bidx[1];
    }
    __syncthreads();
    if (tid < BMW) {
        float bs = sF[tid * 8];
        int   bi = sI[tid * 8];
        #pragma unroll
        for (int q = 1; q < 8; ++q) {
            const float s  = sF[tid * 8 + q];
            const int   ix = sI[tid * 8 + q];
            if (s > bs || (s == bs && ix < bi)) { bs = s; bi = ix; }
        }
        widx[tid] = bi;
    }
    __syncthreads();

    // ---- gather winning codebook rows (L2-hot) ----
    const float4* cb4  = reinterpret_cast<const float4*>(cb);
    float4*       out4 = reinterpret_cast<float4*>(out) + (size_t)blockIdx.x * (BMW * 32);
    #pragma unroll
    for (int i = 0; i < 8; ++i) {
        const int f = i * 256 + tid;          // 0..2047
        const int wv = f >> 5, c = f & 31;
        out4[f] = __ldg(&cb4[(size_t)widx[wv] * 32 + c]);
    }
}

// ---------------------------------------------------------------------------
extern "C" void kernel_launch(void* const* d_in, const int* in_sizes, int n_in,
                              void* d_out, int out_size) {
    const float* ze = (const float*)d_in[0];
    const float* cb = (const float*)d_in[1];
    float* out = (float*)d_out;

    const int M = in_sizes[0] / D;   // 65536
    const int K = in_sizes[1] / D;   // 2048

    cudaFuncSetAttribute(vq_mma_kernel, cudaFuncAttributeMaxDynamicSharedMemorySize,
                         SMEM_TOTAL);

    cnorm_kernel<<<(K + 7) / 8, NTHR>>>(cb, K);
    pack_cb_kernel<<<(K * D + NTHR - 1) / NTHR, NTHR>>>(cb, K);
    vq_mma_kernel<<<M / BMW, NTHR, SMEM_TOTAL>>>(ze, cb, out, K / NTE);
}

// round 12
// speedup vs baseline: 1.1165x; 1.0098x over previous
#include <cuda_runtime.h>
#include <cuda_bf16.h>
#include <math_constants.h>
#include <cstdint>

// ----------------------------------------------------------------------------
// Window VQ via mma.sync bf16 tensor cores (base ISA, works on sm_100 target).
//   argmin_k ||z - c_k||^2 == argmax_k ( z.c_k - 0.5*||c_k||^2 )
// fp32 emulated as 3-way bf16 split (x = x1+x2+x3); 6 cross-products
// {11,12,21,22,13,31} accumulated in fp32 -> error ~2e-7, exact argmin.
//
// R12 = R11 + 2 CTAs/SM for latency hiding (4 warps/SMSP):
//  - smem diet: staged B tile 32 entries (24KB buffers), total 104KB
//  - reg diet: only A1 register-resident; A2/A3 via in-loop ldmatrix
// ----------------------------------------------------------------------------

#define D       128
#define BMW     64      // windows per CTA
#define NTE     32      // codebook entries per staged tile
#define NTHR    256

// smem byte offsets: A 48KB | B0 24KB | B1 24KB | cnorm 8KB = 104KB
#define OFF_A    0
#define OFF_B0   49152
#define OFF_B1   73728
#define OFF_CN   98304
#define SMEM_TOTAL 106496

__device__ float g_cnorm[4096];
// packed B splits: [nt 0..63][s 0..2][j 0..3][kt 0..15][r 0..7][c 0..7] bf16, 1.5MB
__device__ __align__(16) __nv_bfloat16 g_Bpk[64 * 3 * 4 * 16 * 64];

// ---------------------------------------------------------------------------
__global__ void cnorm_kernel(const float* __restrict__ cb, int K) {
    int row  = blockIdx.x * 8 + (threadIdx.x >> 5);
    int lane = threadIdx.x & 31;
    if (row < K) {
        const float4 v = reinterpret_cast<const float4*>(cb + (size_t)row * D)[lane];
        float s = v.x * v.x + v.y * v.y + v.z * v.z + v.w * v.w;
        #pragma unroll
        for (int o = 16; o; o >>= 1) s += __shfl_xor_sync(0xffffffffu, s, o);
        if (lane == 0) g_cnorm[row] = 0.5f * s;
    }
}

__device__ __forceinline__ void split3(float x, __nv_bfloat16& h1,
                                       __nv_bfloat16& h2, __nv_bfloat16& h3) {
    h1 = __float2bfloat16(x);
    const float r1 = x - __bfloat162float(h1);
    h2 = __float2bfloat16(r1);
    h3 = __float2bfloat16(r1 - __bfloat162float(h2));
}

// Pack codebook: entry n, dim k -> per (nt=n/32, split, j=(n/8)%4, kt=k/8):
// 8x8 bf16 tile (row r = n%8, col c = k%8) stored as 128B contiguous.
__global__ void pack_cb_kernel(const float* __restrict__ cb, int K) {
    const int idx = blockIdx.x * NTHR + threadIdx.x;
    if (idx >= K * D) return;
    const int n = idx >> 7, k = idx & 127;
    __nv_bfloat16 h1, h2, h3;
    split3(cb[idx], h1, h2, h3);
    const int nt = n >> 5, j = (n >> 3) & 3, r = n & 7;
    const int kt = k >> 3, c = k & 7;
    const size_t off = (size_t)nt * 12288 + j * 1024 + kt * 64 + r * 8 + c;
    g_Bpk[off]         = h1;
    g_Bpk[off + 4096]  = h2;
    g_Bpk[off + 8192]  = h3;
}

// ---------------------------------------------------------------------------
#define LDSM4(r0, r1, r2, r3, a) \
    asm volatile("ldmatrix.sync.aligned.m8n8.x4.shared.b16 {%0,%1,%2,%3}, [%4];" \
                 : "=r"(r0), "=r"(r1), "=r"(r2), "=r"(r3) : "r"(a))

#define MMA(ac, A0, A1, A2, A3, B0, B1) \
    asm volatile("mma.sync.aligned.m16n8k16.row.col.f32.bf16.bf16.f32 " \
                 "{%0,%1,%2,%3},{%4,%5,%6,%7},{%8,%9},{%0,%1,%2,%3};" \
                 : "+f"(ac[0]), "+f"(ac[1]), "+f"(ac[2]), "+f"(ac[3]) \
                 : "r"(A0), "r"(A1), "r"(A2), "r"(A3), "r"(B0), "r"(B1))

__device__ __forceinline__ uint32_t smem_u32(const void* p) {
    uint32_t a;
    asm("{ .reg .u64 t; cvta.to.shared.u64 t, %1; cvt.u32.u64 %0, t; }" : "=r"(a) : "l"(p));
    return a;
}
__device__ __forceinline__ void cp_async16(uint32_t saddr, const void* g) {
    asm volatile("cp.async.cg.shared.global [%0], [%1], 16;" :: "r"(saddr), "l"(g));
}

// load 8 k-step B fragments (16 regs) for one n8 region (2KB of tiles).
// addr MUST already include lane*16 (per-lane row address for ldmatrix).
__device__ __forceinline__ void load_bfrags(uint32_t* b, uint32_t addr) {
    #pragma unroll
    for (int q = 0; q < 4; ++q)
        LDSM4(b[q * 4 + 0], b[q * 4 + 1], b[q * 4 + 2], b[q * 4 + 3], addr + q * 512);
}

// pass with register-resident A fragments
__device__ __forceinline__ void mma_pass(float (*acc)[4], const uint32_t (*af)[4],
                                         const uint32_t* b0, const uint32_t* b1) {
    #pragma unroll
    for (int kk = 0; kk < 8; ++kk) {
        MMA(acc[0], af[kk][0], af[kk][1], af[kk][2], af[kk][3], b0[2 * kk], b0[2 * kk + 1]);
        MMA(acc[1], af[kk][0], af[kk][1], af[kk][2], af[kk][3], b1[2 * kk], b1[2 * kk + 1]);
    }
}

// pass with A fragments streamed from smem via ldmatrix (A2/A3)
__device__ __forceinline__ void mma_pass_sm(float (*acc)[4], uint32_t abase,
                                            const uint32_t* b0, const uint32_t* b1) {
    #pragma unroll
    for (int kk = 0; kk < 8; ++kk) {
        uint32_t t0, t1, t2, t3;
        LDSM4(t0, t1, t2, t3, abase + kk * 512);
        MMA(acc[0], t0, t1, t2, t3, b0[2 * kk], b0[2 * kk + 1]);
        MMA(acc[1], t0, t1, t2, t3, b1[2 * kk], b1[2 * kk + 1]);
    }
}

// ---------------------------------------------------------------------------
// Warp w: m-tile = w&3 (rows 16*(w&3)..+15), n-half = w>>2 (n8 groups
// {2*(w>>2), 2*(w>>2)+1} of the 4 groups in each 32-entry staged tile).
// ---------------------------------------------------------------------------
__global__ __launch_bounds__(NTHR, 2)
void vq_mma_kernel(const float* __restrict__ ze,
                   const float* __restrict__ cb,
                   float* __restrict__ out,
                   int ntiles) {
    extern __shared__ __align__(16) char smem[];
    float* Cn = reinterpret_cast<float*>(smem + OFF_CN);

    const uint32_t sbase = smem_u32(smem);
    const int tid  = threadIdx.x;
    const int w    = tid >> 5;
    const int lane = tid & 31;
    const int g0   = (w >> 2) * 2;        // first n8 group for this warp

    // ---- 1. build A split tiles in smem (ldmatrix-packed, mma subtile order) ----
    {
        const float* zsrc = ze + (size_t)blockIdx.x * (BMW * D);
        for (int i = tid; i < BMW * D; i += NTHR) {
            const int m = i >> 7, k = i & 127;
            __nv_bfloat16 h1, h2, h3;
            split3(zsrc[i], h1, h2, h3);
            const int t = ((m >> 3) & 1) | (((k >> 3) & 1) << 1);
            const int base = (m >> 4) * 4096 + (k >> 4) * 512 + t * 128
                           + (m & 7) * 16 + (k & 7) * 2;
            *reinterpret_cast<__nv_bfloat16*>(smem + base)         = h1;
            *reinterpret_cast<__nv_bfloat16*>(smem + base + 16384) = h2;
            *reinterpret_cast<__nv_bfloat16*>(smem + base + 32768) = h3;
        }
        for (int i = tid; i < ntiles * NTE; i += NTHR) Cn[i] = g_cnorm[i];
    }
    __syncthreads();

    // ---- 2. A1 fragments resident in registers (m-tile = w&3) ----
    uint32_t a1f[8][4];
    const uint32_t abase = sbase + (w & 3) * 4096 + lane * 16;
    #pragma unroll
    for (int kk = 0; kk < 8; ++kk)
        LDSM4(a1f[kk][0], a1f[kk][1], a1f[kk][2], a1f[kk][3], abase + kk * 512);

    // ---- 3. prologue: stage B tile 0 (24KB) ----
    {
        const char* src = reinterpret_cast<const char*>(g_Bpk);
        #pragma unroll
        for (int u = 0; u < 6; ++u)
            cp_async16(sbase + OFF_B0 + u * 4096 + tid * 16, src + u * 4096 + tid * 16);
        asm volatile("cp.async.commit_group;");
    }

    float best[2] = {-CUDART_INF_F, -CUDART_INF_F};
    int   bidx[2] = {0, 0};

    for (int nt = 0; nt < ntiles; ++nt) {
        asm volatile("cp.async.wait_group 0;");
        __syncthreads();

        if (nt + 1 < ntiles) {
            const char* src = reinterpret_cast<const char*>(g_Bpk) + (size_t)(nt + 1) * 24576;
            const uint32_t dst = sbase + (((nt + 1) & 1) ? OFF_B1 : OFF_B0);
            #pragma unroll
            for (int u = 0; u < 6; ++u)
                cp_async16(dst + u * 4096 + tid * 16, src + u * 4096 + tid * 16);
            asm volatile("cp.async.commit_group;");
        }

        // per-lane base inside the current B buffer
        const uint32_t bb = sbase + ((nt & 1) ? OFF_B1 : OFF_B0) + lane * 16;
        const int ntbase = nt * NTE;

        float acc[2][4] = {{0.f, 0.f, 0.f, 0.f}, {0.f, 0.f, 0.f, 0.f}};
        uint32_t b0r[16], b1r[16];

        // split s=0 of B: passes (A1,B1), (A2,B1), (A3,B1)
        load_bfrags(b0r, bb + g0 * 2048);
        load_bfrags(b1r, bb + (g0 + 1) * 2048);
        mma_pass(acc, a1f, b0r, b1r);
        mma_pass_sm(acc, abase + 16384, b0r, b1r);
        mma_pass_sm(acc, abase + 32768, b0r, b1r);

        // split s=1 of B: passes (A1,B2), (A2,B2)
        load_bfrags(b0r, bb + 8192 + g0 * 2048);
        load_bfrags(b1r, bb + 8192 + (g0 + 1) * 2048);
        mma_pass(acc, a1f, b0r, b1r);
        mma_pass_sm(acc, abase + 16384, b0r, b1r);

        // split s=2 of B: pass (A1,B3)
        load_bfrags(b0r, bb + 16384 + g0 * 2048);
        load_bfrags(b1r, bb + 16384 + (g0 + 1) * 2048);
        mma_pass(acc, a1f, b0r, b1r);

        // ---- epilogue: scores + running argmax (ascending n) ----
        #pragma unroll
        for (int js = 0; js < 2; ++js) {
            const int n0 = ntbase + (g0 + js) * 8 + 2 * (lane & 3);
            const float2 cn2 = *reinterpret_cast<const float2*>(&Cn[n0]);
            const float s00 = acc[js][0] - cn2.x;   // row g,   n0
            const float s01 = acc[js][1] - cn2.y;   // row g,   n0+1
            const float s10 = acc[js][2] - cn2.x;   // row g+8, n0
            const float s11 = acc[js][3] - cn2.y;
            if (s00 > best[0]) { best[0] = s00; bidx[0] = n0; }
            if (s01 > best[0]) { best[0] = s01; bidx[0] = n0 + 1; }
            if (s10 > best[1]) { best[1] = s10; bidx[1] = n0; }
            if (s11 > best[1]) { best[1] = s11; bidx[1] = n0 + 1; }
        }
    }

    // ---- reduce 8 candidates per window (4 lane-quads x 2 n-halves) ----
    float* sF   = reinterpret_cast<float*>(smem + OFF_B0);         // [64][8]
    int*   sI   = reinterpret_cast<int*>(smem + OFF_B0 + 2048);
    int*   widx = reinterpret_cast<int*>(smem + OFF_B0 + 4096);
    __syncthreads();      // all warps done reading B buffers
    {
        const int m0  = 16 * (w & 3) + (lane >> 2);
        const int col = (w >> 2) * 4 + (lane & 3);
        sF[m0 * 8 + col] = best[0];        sI[m0 * 8 + col] = bidx[0];
        sF[(m0 + 8) * 8 + col] = best[1];  sI[(m0 + 8) * 8 + col] = bidx[1];
    }
    __syncthreads();
    if (tid < BMW) {
        float bs = sF[tid * 8];
        int   bi = sI[tid * 8];
        #pragma unroll
        for (int q = 1; q < 8; ++q) {
            const float s  = sF[tid * 8 + q];
            const int   ix = sI[tid * 8 + q];
            if (s > bs || (s == bs && ix < bi)) { bs = s; bi = ix; }
        }
        widx[tid] = bi;
    }
    __syncthreads();

    // ---- gather winning codebook rows (L2-hot) ----
    const float4* cb4  = reinterpret_cast<const float4*>(cb);
    float4*       out4 = reinterpret_cast<float4*>(out) + (size_t)blockIdx.x * (BMW * 32);
    #pragma unroll
    for (int i = 0; i < 8; ++i) {
        const int f = i * 256 + tid;          // 0..2047
        const int wv = f >> 5, c = f & 31;
        out4[f] = __ldg(&cb4[(size_t)widx[wv] * 32 + c]);
    }
}

// ---------------------------------------------------------------------------
extern "C" void kernel_launch(void* const* d_in, const int* in_sizes, int n_in,
                              void* d_out, int out_size) {
    const float* ze = (const float*)d_in[0];
    const float* cb = (const float*)d_in[1];
    float* out = (float*)d_out;

    const int M = in_sizes[0] / D;   // 65536
    const int K = in_sizes[1] / D;   // 2048

    cudaFuncSetAttribute(vq_mma_kernel, cudaFuncAttributeMaxDynamicSharedMemorySize,
                         SMEM_TOTAL);

    cnorm_kernel<<<(K + 7) / 8, NTHR>>>(cb, K);
    pack_cb_kernel<<<(K * D + NTHR - 1) / NTHR, NTHR>>>(cb, K);
    vq_mma_kernel<<<M / BMW, NTHR, SMEM_TOTAL>>>(ze, cb, out, K / NTE);
}

// round 13
// speedup vs baseline: 2.0986x; 1.8796x over previous
#include <cuda_runtime.h>
#include <cuda_fp16.h>
#include <math_constants.h>
#include <cstdint>

// ----------------------------------------------------------------------------
// Window VQ via mma.sync fp16 tensor cores (base ISA, works on sm_100 target).
//   argmin_k ||z - c_k||^2 == argmax_k ( z.c_k - 0.5*||c_k||^2 )
// fp32 emulated as 2-way fp16 split: x = x1 + x2/2048, with x2 stored
// pre-scaled by 2^11 (no denormals). 3 passes {11 -> accM, 21,12 -> accR},
// score = accM + accR*2^-11. Dropped term x2*y2 ~ 2^-22 -> ~2e-6 score error,
// at fp32 accumulation-noise level (empirically flip-free).
//
// R13 = R12 structure with HALF the MMA instructions (3 passes vs 6).
// ----------------------------------------------------------------------------

#define D       128
#define BMW     64      // windows per CTA
#define NTE     64      // codebook entries per staged tile
#define NTHR    256

#define RSCALE  4.8828125e-4f   // 2^-11

// smem byte offsets: A 32KB | B0 32KB | B1 32KB | cnorm 8KB = 104KB
#define OFF_A    0
#define OFF_B0   32768
#define OFF_B1   65536
#define OFF_CN   98304
#define SMEM_TOTAL 106496

__device__ float g_cnorm[4096];
// packed B splits: [nt 0..31][s 0..1][j 0..7][kt 0..15][r 0..7][c 0..7] fp16, 1MB
__device__ __align__(16) __half g_Bpk[32 * 2 * 8 * 16 * 64];

// ---------------------------------------------------------------------------
__global__ void cnorm_kernel(const float* __restrict__ cb, int K) {
    int row  = blockIdx.x * 8 + (threadIdx.x >> 5);
    int lane = threadIdx.x & 31;
    if (row < K) {
        const float4 v = reinterpret_cast<const float4*>(cb + (size_t)row * D)[lane];
        float s = v.x * v.x + v.y * v.y + v.z * v.z + v.w * v.w;
        #pragma unroll
        for (int o = 16; o; o >>= 1) s += __shfl_xor_sync(0xffffffffu, s, o);
        if (lane == 0) g_cnorm[row] = 0.5f * s;
    }
}

__device__ __forceinline__ void split2(float x, __half& h1, __half& h2) {
    h1 = __float2half_rn(x);
    h2 = __float2half_rn((x - __half2float(h1)) * 2048.0f);   // scaled residual
}

// Pack codebook: entry n, dim k -> per (nt=n/64, split, j=(n/8)%8, kt=k/8):
// 8x8 fp16 tile (row r = n%8, col c = k%8) stored as 128B contiguous.
__global__ void pack_cb_kernel(const float* __restrict__ cb, int K) {
    const int idx = blockIdx.x * NTHR + threadIdx.x;
    if (idx >= K * D) return;
    const int n = idx >> 7, k = idx & 127;
    __half h1, h2;
    split2(cb[idx], h1, h2);
    const int nt = n >> 6, j = (n >> 3) & 7, r = n & 7;
    const int kt = k >> 3, c = k & 7;
    const size_t off = (size_t)nt * 16384 + j * 1024 + kt * 64 + r * 8 + c;
    g_Bpk[off]        = h1;
    g_Bpk[off + 8192] = h2;
}

// ---------------------------------------------------------------------------
#define LDSM4(r0, r1, r2, r3, a) \
    asm volatile("ldmatrix.sync.aligned.m8n8.x4.shared.b16 {%0,%1,%2,%3}, [%4];" \
                 : "=r"(r0), "=r"(r1), "=r"(r2), "=r"(r3) : "r"(a))

#define MMA(ac, A0, A1, A2, A3, B0, B1) \
    asm volatile("mma.sync.aligned.m16n8k16.row.col.f32.f16.f16.f32 " \
                 "{%0,%1,%2,%3},{%4,%5,%6,%7},{%8,%9},{%0,%1,%2,%3};" \
                 : "+f"(ac[0]), "+f"(ac[1]), "+f"(ac[2]), "+f"(ac[3]) \
                 : "r"(A0), "r"(A1), "r"(A2), "r"(A3), "r"(B0), "r"(B1))

__device__ __forceinline__ uint32_t smem_u32(const void* p) {
    uint32_t a;
    asm("{ .reg .u64 t; cvta.to.shared.u64 t, %1; cvt.u32.u64 %0, t; }" : "=r"(a) : "l"(p));
    return a;
}
__device__ __forceinline__ void cp_async16(uint32_t saddr, const void* g) {
    asm volatile("cp.async.cg.shared.global [%0], [%1], 16;" :: "r"(saddr), "l"(g));
}

// load 8 k-step B fragments (16 regs) for one n8 region (2KB of tiles).
// addr MUST already include lane*16 (per-lane row address for ldmatrix).
__device__ __forceinline__ void load_bfrags(uint32_t* b, uint32_t addr) {
    #pragma unroll
    for (int q = 0; q < 4; ++q)
        LDSM4(b[q * 4 + 0], b[q * 4 + 1], b[q * 4 + 2], b[q * 4 + 3], addr + q * 512);
}

// pass with register-resident A fragments
__device__ __forceinline__ void mma_pass(float (*acc)[4], const uint32_t (*af)[4],
                                         const uint32_t* b0, const uint32_t* b1) {
    #pragma unroll
    for (int kk = 0; kk < 8; ++kk) {
        MMA(acc[0], af[kk][0], af[kk][1], af[kk][2], af[kk][3], b0[2 * kk], b0[2 * kk + 1]);
        MMA(acc[1], af[kk][0], af[kk][1], af[kk][2], af[kk][3], b1[2 * kk], b1[2 * kk + 1]);
    }
}

// pass with A fragments streamed from smem via ldmatrix (A2')
__device__ __forceinline__ void mma_pass_sm(float (*acc)[4], uint32_t abase,
                                            const uint32_t* b0, const uint32_t* b1) {
    #pragma unroll
    for (int kk = 0; kk < 8; ++kk) {
        uint32_t t0, t1, t2, t3;
        LDSM4(t0, t1, t2, t3, abase + kk * 512);
        MMA(acc[0], t0, t1, t2, t3, b0[2 * kk], b0[2 * kk + 1]);
        MMA(acc[1], t0, t1, t2, t3, b1[2 * kk], b1[2 * kk + 1]);
    }
}

// ---------------------------------------------------------------------------
// Warp w: m-tile = w&3 (rows 16*(w&3)..+15), n-half = w>>2 (n8 groups
// 4*(w>>2) + {0..3} of the 8 groups in each 64-entry staged tile).
// ---------------------------------------------------------------------------
__global__ __launch_bounds__(NTHR, 2)
void vq_mma_kernel(const float* __restrict__ ze,
                   const float* __restrict__ cb,
                   float* __restrict__ out,
                   int ntiles) {
    extern __shared__ __align__(16) char smem[];
    float* Cn = reinterpret_cast<float*>(smem + OFF_CN);

    const uint32_t sbase = smem_u32(smem);
    const int tid  = threadIdx.x;
    const int w    = tid >> 5;
    const int lane = tid & 31;

    // ---- 1. build A split tiles in smem (ldmatrix-packed, mma subtile order) ----
    {
        const float* zsrc = ze + (size_t)blockIdx.x * (BMW * D);
        for (int i = tid; i < BMW * D; i += NTHR) {
            const int m = i >> 7, k = i & 127;
            __half h1, h2;
            split2(zsrc[i], h1, h2);
            const int t = ((m >> 3) & 1) | (((k >> 3) & 1) << 1);
            const int base = (m >> 4) * 4096 + (k >> 4) * 512 + t * 128
                           + (m & 7) * 16 + (k & 7) * 2;
            *reinterpret_cast<__half*>(smem + base)         = h1;
            *reinterpret_cast<__half*>(smem + base + 16384) = h2;
        }
        for (int i = tid; i < ntiles * NTE; i += NTHR) Cn[i] = g_cnorm[i];
    }
    __syncthreads();

    // ---- 2. A1 fragments resident in registers (m-tile = w&3) ----
    uint32_t a1f[8][4];
    const uint32_t abase = sbase + (w & 3) * 4096 + lane * 16;
    #pragma unroll
    for (int kk = 0; kk < 8; ++kk)
        LDSM4(a1f[kk][0], a1f[kk][1], a1f[kk][2], a1f[kk][3], abase + kk * 512);

    // ---- 3. prologue: stage B tile 0 (32KB) ----
    {
        const char* src = reinterpret_cast<const char*>(g_Bpk);
        #pragma unroll
        for (int u = 0; u < 8; ++u)
            cp_async16(sbase + OFF_B0 + u * 4096 + tid * 16, src + u * 4096 + tid * 16);
        asm volatile("cp.async.commit_group;");
    }

    float best[2] = {-CUDART_INF_F, -CUDART_INF_F};
    int   bidx[2] = {0, 0};

    for (int nt = 0; nt < ntiles; ++nt) {
        asm volatile("cp.async.wait_group 0;");
        __syncthreads();

        if (nt + 1 < ntiles) {
            const char* src = reinterpret_cast<const char*>(g_Bpk) + (size_t)(nt + 1) * 32768;
            const uint32_t dst = sbase + (((nt + 1) & 1) ? OFF_B1 : OFF_B0);
            #pragma unroll
            for (int u = 0; u < 8; ++u)
                cp_async16(dst + u * 4096 + tid * 16, src + u * 4096 + tid * 16);
            asm volatile("cp.async.commit_group;");
        }

        // per-lane base inside the current B buffer
        const uint32_t bb = sbase + ((nt & 1) ? OFF_B1 : OFF_B0) + lane * 16;
        const int ntbase = nt * NTE;

        #pragma unroll
        for (int jj = 0; jj < 2; ++jj) {
            const int g0 = (w >> 2) * 4 + 2 * jj;         // first n8 group
            float accM[2][4] = {{0.f, 0.f, 0.f, 0.f}, {0.f, 0.f, 0.f, 0.f}};
            float accR[2][4] = {{0.f, 0.f, 0.f, 0.f}, {0.f, 0.f, 0.f, 0.f}};
            uint32_t b0r[16], b1r[16];

            // split s=0 of B (B1): passes (A1,B1)->accM, (A2',B1)->accR
            load_bfrags(b0r, bb + g0 * 2048);
            load_bfrags(b1r, bb + (g0 + 1) * 2048);
            mma_pass(accM, a1f, b0r, b1r);
            mma_pass_sm(accR, abase + 16384, b0r, b1r);

            // split s=1 of B (B2'): pass (A1,B2')->accR
            load_bfrags(b0r, bb + 16384 + g0 * 2048);
            load_bfrags(b1r, bb + 16384 + (g0 + 1) * 2048);
            mma_pass(accR, a1f, b0r, b1r);

            // ---- epilogue: score = accM + accR*2^-11 - cn, running argmax ----
            #pragma unroll
            for (int js = 0; js < 2; ++js) {
                const int n0 = ntbase + (g0 + js) * 8 + 2 * (lane & 3);
                const float2 cn2 = *reinterpret_cast<const float2*>(&Cn[n0]);
                const float s00 = fmaf(accR[js][0], RSCALE, accM[js][0]) - cn2.x;
                const float s01 = fmaf(accR[js][1], RSCALE, accM[js][1]) - cn2.y;
                const float s10 = fmaf(accR[js][2], RSCALE, accM[js][2]) - cn2.x;
                const float s11 = fmaf(accR[js][3], RSCALE, accM[js][3]) - cn2.y;
                if (s00 > best[0]) { best[0] = s00; bidx[0] = n0; }
                if (s01 > best[0]) { best[0] = s01; bidx[0] = n0 + 1; }
                if (s10 > best[1]) { best[1] = s10; bidx[1] = n0; }
                if (s11 > best[1]) { best[1] = s11; bidx[1] = n0 + 1; }
            }
        }
    }

    // ---- reduce 8 candidates per window (4 lane-quads x 2 n-halves) ----
    float* sF   = reinterpret_cast<float*>(smem + OFF_B0);         // [64][8]
    int*   sI   = reinterpret_cast<int*>(smem + OFF_B0 + 2048);
    int*   widx = reinterpret_cast<int*>(smem + OFF_B0 + 4096);
    __syncthreads();      // all warps done reading B buffers
    {
        const int m0  = 16 * (w & 3) + (lane >> 2);
        const int col = (w >> 2) * 4 + (lane & 3);
        sF[m0 * 8 + col] = best[0];        sI[m0 * 8 + col] = bidx[0];
        sF[(m0 + 8) * 8 + col] = best[1];  sI[(m0 + 8) * 8 + col] = bidx[1];
    }
    __syncthreads();
    if (tid < BMW) {
        float bs = sF[tid * 8];
        int   bi = sI[tid * 8];
        #pragma unroll
        for (int q = 1; q < 8; ++q) {
            const float s  = sF[tid * 8 + q];
            const int   ix = sI[tid * 8 + q];
            if (s > bs || (s == bs && ix < bi)) { bs = s; bi = ix; }
        }
        widx[tid] = bi;
    }
    __syncthreads();

    // ---- gather winning codebook rows (L2-hot) ----
    const float4* cb4  = reinterpret_cast<const float4*>(cb);
    float4*       out4 = reinterpret_cast<float4*>(out) + (size_t)blockIdx.x * (BMW * 32);
    #pragma unroll
    for (int i = 0; i < 8; ++i) {
        const int f = i * 256 + tid;          // 0..2047
        const int wv = f >> 5, c = f & 31;
        out4[f] = __ldg(&cb4[(size_t)widx[wv] * 32 + c]);
    }
}

// ---------------------------------------------------------------------------
extern "C" void kernel_launch(void* const* d_in, const int* in_sizes, int n_in,
                              void* d_out, int out_size) {
    const float* ze = (const float*)d_in[0];
    const float* cb = (const float*)d_in[1];
    float* out = (float*)d_out;

    const int M = in_sizes[0] / D;   // 65536
    const int K = in_sizes[1] / D;   // 2048

    cudaFuncSetAttribute(vq_mma_kernel, cudaFuncAttributeMaxDynamicSharedMemorySize,
                         SMEM_TOTAL);

    cnorm_kernel<<<(K + 7) / 8, NTHR>>>(cb, K);
    pack_cb_kernel<<<(K * D + NTHR - 1) / NTHR, NTHR>>>(cb, K);
    vq_mma_kernel<<<M / BMW, NTHR, SMEM_TOTAL>>>(ze, cb, out, K / NTE);
}